// round 15
// baseline (speedup 1.0000x reference)
#include <cuda_runtime.h>
#include <cuda_bf16.h>
#include <cstdint>
#include <math.h>

#define DMODEL 1024
#define IMGM   512
#define NHEADS 16
#define DK     64
#define BATCH  8
#define LQ_    2048
#define LKV_   1024
#define MQ   (BATCH * LQ_)    // 16384
#define MKV  (BATCH * LKV_)   // 8192

// ---------------- scratch (static device globals; no allocs allowed) -------
__device__ __nv_bfloat16 g_q_hi[(size_t)MQ  * DMODEL], g_q_lo[(size_t)MQ  * DMODEL];
__device__ __nv_bfloat16 g_k_hi[(size_t)MKV * IMGM ], g_k_lo[(size_t)MKV * IMGM ];
__device__ __nv_bfloat16 g_v_hi[(size_t)MKV * IMGM ], g_v_lo[(size_t)MKV * IMGM ];
__device__ __nv_bfloat16 g_Qph[(size_t)MQ  * DMODEL], g_Qpl[(size_t)MQ  * DMODEL];
__device__ __nv_bfloat16 g_Kph[(size_t)MKV * DMODEL], g_Kpl[(size_t)MKV * DMODEL];
__device__ __nv_bfloat16 g_Vph[(size_t)MKV * DMODEL], g_Vpl[(size_t)MKV * DMODEL];
__device__ __nv_bfloat16 g_c_hi[(size_t)MQ  * DMODEL], g_c_lo[(size_t)MQ  * DMODEL];
__device__ __nv_bfloat16 g_Wqt_hi[DMODEL * DMODEL], g_Wqt_lo[DMODEL * DMODEL];
__device__ __nv_bfloat16 g_Wkt_hi[DMODEL * IMGM ], g_Wkt_lo[DMODEL * IMGM ];
__device__ __nv_bfloat16 g_Wvt_hi[DMODEL * IMGM ], g_Wvt_lo[DMODEL * IMGM ];
__device__ __nv_bfloat16 g_Wot_hi[DMODEL * DMODEL], g_Wot_lo[DMODEL * DMODEL];

// ---------------- PTX helpers ----------------------------------------------
__device__ __forceinline__ uint32_t smem_u32(const void* p) {
    uint32_t a;
    asm("{ .reg .u64 t; cvta.to.shared.u64 t, %1; cvt.u32.u64 %0, t; }"
        : "=r"(a) : "l"(p));
    return a;
}
__device__ __forceinline__ void ldsm_x4(uint32_t* r, uint32_t addr) {
    asm volatile("ldmatrix.sync.aligned.m8n8.x4.shared.b16 {%0,%1,%2,%3}, [%4];"
                 : "=r"(r[0]), "=r"(r[1]), "=r"(r[2]), "=r"(r[3]) : "r"(addr));
}
__device__ __forceinline__ void ldsm_x2(uint32_t* r, uint32_t addr) {
    asm volatile("ldmatrix.sync.aligned.m8n8.x2.shared.b16 {%0,%1}, [%2];"
                 : "=r"(r[0]), "=r"(r[1]) : "r"(addr));
}
__device__ __forceinline__ void ldsm_x2_trans(uint32_t* r, uint32_t addr) {
    asm volatile("ldmatrix.sync.aligned.m8n8.x2.trans.shared.b16 {%0,%1}, [%2];"
                 : "=r"(r[0]), "=r"(r[1]) : "r"(addr));
}
__device__ __forceinline__ void mma_bf16(float* c, const uint32_t* a, const uint32_t* b) {
    asm volatile(
        "mma.sync.aligned.m16n8k16.row.col.f32.bf16.bf16.f32 "
        "{%0,%1,%2,%3}, {%4,%5,%6,%7}, {%8,%9}, {%0,%1,%2,%3};"
        : "+f"(c[0]), "+f"(c[1]), "+f"(c[2]), "+f"(c[3])
        : "r"(a[0]), "r"(a[1]), "r"(a[2]), "r"(a[3]), "r"(b[0]), "r"(b[1]));
}
#define CP_ASYNC16(dst, src) \
    asm volatile("cp.async.cg.shared.global [%0], [%1], 16;" :: "r"(dst), "l"(src) : "memory")
#define CP_COMMIT()  asm volatile("cp.async.commit_group;" ::: "memory")
#define CP_WAIT(n)   asm volatile("cp.async.wait_group %0;" :: "n"(n) : "memory")

__device__ __forceinline__ void bf16_split_pack(float a, float b,
                                                uint32_t& hi, uint32_t& lo) {
    __nv_bfloat16 ha = __float2bfloat16_rn(a), hb = __float2bfloat16_rn(b);
    float ra = a - __bfloat162float(ha);
    float rb = b - __bfloat162float(hb);
    __nv_bfloat162 hp, lp;
    hp.x = ha; hp.y = hb;
    lp.x = __float2bfloat16_rn(ra); lp.y = __float2bfloat16_rn(rb);
    hi = *reinterpret_cast<uint32_t*>(&hp);
    lo = *reinterpret_cast<uint32_t*>(&lp);
}

// ---------------------------------------------------------------------------
// HMMA bf16 GEMM core (round-7/14 best): CTA 128(M) x 256(N), BK=64,
// 256 threads, 8 warps 2(M) x 4(N), warp tile 64x64. Double-buffered cp.async.
// ---------------------------------------------------------------------------
#define GT_PAD      72
#define GT_ATILE_B  (128 * GT_PAD * 2)   // 18432
#define GT_BTILE_B  (256 * GT_PAD * 2)   // 36864
#define GT_STAGE_B  (2 * GT_ATILE_B + 2 * GT_BTILE_B)   // 110592
#define GT_SMEM_TOTAL (2 * GT_STAGE_B)                  // 221184

__device__ __forceinline__ void gt_load_stage(
    uint32_t stage, const __nv_bfloat16* __restrict__ Ah,
    const __nv_bfloat16* __restrict__ Al, const __nv_bfloat16* __restrict__ Bh,
    const __nv_bfloat16* __restrict__ Bl,
    int bm, int bn, int K, int k0, int tid)
{
    #pragma unroll
    for (int i = 0; i < 24; i++) {
        int cid = i * 256 + tid;        // 0..6143
        int ch  = cid & 7;              // 16B chunk within 64-col row
        uint32_t dst;
        const __nv_bfloat16* src;
        if (cid < 2048) {               // A region: hi 0-1023, lo 1024-2047
            int row = (cid >> 3) & 127;
            bool hi = cid < 1024;
            src = (hi ? Ah : Al) + (size_t)(bm + row) * K + k0 + ch * 8;
            dst = stage + (hi ? 0u : (uint32_t)GT_ATILE_B)
                + (uint32_t)(row * GT_PAD + ch * 8) * 2;
        } else {                        // B region: hi 0-2047, lo 2048-4095
            int c2  = cid - 2048;
            int row = (c2 >> 3) & 255;
            bool hi = c2 < 2048;
            src = (hi ? Bh : Bl) + (size_t)(bn + row) * K + k0 + ch * 8;
            dst = stage + 2u * GT_ATILE_B + (hi ? 0u : (uint32_t)GT_BTILE_B)
                + (uint32_t)(row * GT_PAD + ch * 8) * 2;
        }
        CP_ASYNC16(dst, src);
    }
}

__device__ __forceinline__ void gemm_core(
    const __nv_bfloat16* __restrict__ Ah, const __nv_bfloat16* __restrict__ Al,
    const __nv_bfloat16* __restrict__ Bh, const __nv_bfloat16* __restrict__ Bl,
    const float* __restrict__ bias, float* __restrict__ C,
    __nv_bfloat16* __restrict__ Chi, __nv_bfloat16* __restrict__ Clo,
    int N, int K, int bm, int bn, uint32_t sb, int tid)
{
    const int lane = tid & 31;
    const int wid  = tid >> 5;
    const int wm   = wid & 1;
    const int wn   = wid >> 1;

    float acc[4][8][4];
    #pragma unroll
    for (int mt = 0; mt < 4; mt++)
        #pragma unroll
        for (int nt = 0; nt < 8; nt++)
            #pragma unroll
            for (int j = 0; j < 4; j++) acc[mt][nt][j] = 0.f;

    const int KT = K >> 6;

    gt_load_stage(sb, Ah, Al, Bh, Bl, bm, bn, K, 0, tid);
    CP_COMMIT();

    const int a_r = lane & 15;
    const int a_c = (lane >> 4) * 8;
    const int b_row_l = ((lane >> 4) & 1) * 8 + (lane & 7);
    const int b_col_l = ((lane >> 3) & 1) * 8;

    for (int s = 0; s < KT; s++) {
        if (s + 1 < KT) {
            gt_load_stage(sb + ((s + 1) & 1) * GT_STAGE_B, Ah, Al, Bh, Bl,
                          bm, bn, K, (s + 1) * 64, tid);
            CP_COMMIT();
            CP_WAIT(1);
        } else {
            CP_WAIT(0);
        }
        __syncthreads();

        const uint32_t st  = sb + (s & 1) * GT_STAGE_B;
        const uint32_t sAh = st;
        const uint32_t sAl = st + GT_ATILE_B;
        const uint32_t sBh = st + 2 * GT_ATILE_B;
        const uint32_t sBl = st + 2 * GT_ATILE_B + GT_BTILE_B;

        #pragma unroll
        for (int kk = 0; kk < 4; kk++) {
            uint32_t ah[4][4], al[4][4];
            #pragma unroll
            for (int mt = 0; mt < 4; mt++) {
                uint32_t off = (uint32_t)((wm * 64 + mt * 16 + a_r) * GT_PAD
                                          + kk * 16 + a_c) * 2;
                ldsm_x4(ah[mt], sAh + off);
                ldsm_x4(al[mt], sAl + off);
            }
            #pragma unroll
            for (int p = 0; p < 4; p++) {
                uint32_t bh4[4], bl4[4];
                uint32_t off = (uint32_t)((wn * 64 + p * 16 + b_row_l) * GT_PAD
                                          + kk * 16 + b_col_l) * 2;
                ldsm_x4(bh4, sBh + off);
                ldsm_x4(bl4, sBl + off);
                #pragma unroll
                for (int mt = 0; mt < 4; mt++) {
                    mma_bf16(acc[mt][2*p  ], ah[mt], &bh4[0]);
                    mma_bf16(acc[mt][2*p  ], ah[mt], &bl4[0]);
                    mma_bf16(acc[mt][2*p  ], al[mt], &bh4[0]);
                    mma_bf16(acc[mt][2*p+1], ah[mt], &bh4[2]);
                    mma_bf16(acc[mt][2*p+1], ah[mt], &bl4[2]);
                    mma_bf16(acc[mt][2*p+1], al[mt], &bh4[2]);
                }
            }
        }
        __syncthreads();
    }

    const int er = lane >> 2;
    const int ec = (lane & 3) * 2;
    #pragma unroll
    for (int mt = 0; mt < 4; mt++) {
        #pragma unroll
        for (int nt = 0; nt < 8; nt++) {
            int row0 = bm + wm * 64 + mt * 16 + er;
            int col  = bn + wn * 64 + nt * 8 + ec;
            float b0 = bias[col], b1 = bias[col + 1];
            float v00 = acc[mt][nt][0] + b0, v01 = acc[mt][nt][1] + b1;
            float v10 = acc[mt][nt][2] + b0, v11 = acc[mt][nt][3] + b1;
            if (Chi) {
                uint32_t h0, l0, h1, l1;
                bf16_split_pack(v00, v01, h0, l0);
                bf16_split_pack(v10, v11, h1, l1);
                *reinterpret_cast<uint32_t*>(Chi + (size_t)row0 * N + col)       = h0;
                *reinterpret_cast<uint32_t*>(Clo + (size_t)row0 * N + col)       = l0;
                *reinterpret_cast<uint32_t*>(Chi + (size_t)(row0 + 8) * N + col) = h1;
                *reinterpret_cast<uint32_t*>(Clo + (size_t)(row0 + 8) * N + col) = l1;
            } else {
                float2 w0, w1;
                w0.x = v00; w0.y = v01; w1.x = v10; w1.y = v11;
                *reinterpret_cast<float2*>(C + (size_t)row0 * N + col)       = w0;
                *reinterpret_cast<float2*>(C + (size_t)(row0 + 8) * N + col) = w1;
            }
        }
    }
}

// Merged Q/K/V projection: one launch, 1024 CTAs.
__global__ void __launch_bounds__(256, 1) proj_qkv_kernel(
    const __nv_bfloat16* __restrict__ qh, const __nv_bfloat16* __restrict__ ql,
    const __nv_bfloat16* __restrict__ Wqh, const __nv_bfloat16* __restrict__ Wql,
    const float* __restrict__ bq,
    __nv_bfloat16* __restrict__ Qph, __nv_bfloat16* __restrict__ Qpl,
    const __nv_bfloat16* __restrict__ kh, const __nv_bfloat16* __restrict__ kl,
    const __nv_bfloat16* __restrict__ Wkh, const __nv_bfloat16* __restrict__ Wkl,
    const float* __restrict__ bk,
    __nv_bfloat16* __restrict__ Kph, __nv_bfloat16* __restrict__ Kpl,
    const __nv_bfloat16* __restrict__ vh, const __nv_bfloat16* __restrict__ vl,
    const __nv_bfloat16* __restrict__ Wvh, const __nv_bfloat16* __restrict__ Wvl,
    const float* __restrict__ bv,
    __nv_bfloat16* __restrict__ Vph, __nv_bfloat16* __restrict__ Vpl)
{
    extern __shared__ char smem[];
    const uint32_t sb = smem_u32(smem);
    const int tid = threadIdx.x;
    const int gid = blockIdx.x;

    int op, t;
    if (gid < 512)      { op = 0; t = gid; }
    else if (gid < 768) { op = 1; t = gid - 512; }
    else                { op = 2; t = gid - 768; }

    const __nv_bfloat16* Ah = (op == 0) ? qh  : (op == 1) ? kh  : vh;
    const __nv_bfloat16* Al = (op == 0) ? ql  : (op == 1) ? kl  : vl;
    const __nv_bfloat16* Bh = (op == 0) ? Wqh : (op == 1) ? Wkh : Wvh;
    const __nv_bfloat16* Bl = (op == 0) ? Wql : (op == 1) ? Wkl : Wvl;
    const float*        bias = (op == 0) ? bq  : (op == 1) ? bk  : bv;
    __nv_bfloat16*      Chi = (op == 0) ? Qph : (op == 1) ? Kph : Vph;
    __nv_bfloat16*      Clo = (op == 0) ? Qpl : (op == 1) ? Kpl : Vpl;
    const int K = (op == 0) ? DMODEL : IMGM;

    const int bn = (t & 3) * 256;
    const int bm = (t >> 2) * 128;

    gemm_core(Ah, Al, Bh, Bl, bias, nullptr, Chi, Clo, DMODEL, K, bm, bn, sb, tid);
}

// Single GEMM launch (O-projection, fp32 output)
__global__ void __launch_bounds__(256, 1) gemm_tc_kernel(
    const __nv_bfloat16* __restrict__ Ah, const __nv_bfloat16* __restrict__ Al,
    const __nv_bfloat16* __restrict__ Bh, const __nv_bfloat16* __restrict__ Bl,
    const float* __restrict__ bias, float* __restrict__ C,
    int M, int N, int K)
{
    extern __shared__ char smem[];
    const uint32_t sb = smem_u32(smem);
    const int bn = blockIdx.x * 256;
    const int bm = blockIdx.y * 128;
    gemm_core(Ah, Al, Bh, Bl, bias, C, nullptr, nullptr, N, K, bm, bn, sb, threadIdx.x);
}

// ---------------------------------------------------------------------------
// Merged fp32 -> bf16 hi/lo split for q, k, v (one launch)
// ---------------------------------------------------------------------------
#define Q4  (MQ  * DMODEL / 4)
#define KV4 (MKV * IMGM  / 4)

__global__ void __launch_bounds__(256) split_all_kernel(
    const float* __restrict__ q, __nv_bfloat16* __restrict__ qh, __nv_bfloat16* __restrict__ ql,
    const float* __restrict__ k, __nv_bfloat16* __restrict__ kh, __nv_bfloat16* __restrict__ kl,
    const float* __restrict__ v, __nv_bfloat16* __restrict__ vh, __nv_bfloat16* __restrict__ vl)
{
    int i = blockIdx.x * 256 + threadIdx.x;
    const float* x; __nv_bfloat16 *hi, *lo; int idx;
    if (i < Q4)                { x = q; hi = qh; lo = ql; idx = i; }
    else if (i < Q4 + KV4)     { x = k; hi = kh; lo = kl; idx = i - Q4; }
    else if (i < Q4 + 2 * KV4) { x = v; hi = vh; lo = vl; idx = i - Q4 - KV4; }
    else return;
    float4 val = reinterpret_cast<const float4*>(x)[idx];
    uint32_t h0, l0, h1, l1;
    bf16_split_pack(val.x, val.y, h0, l0);
    bf16_split_pack(val.z, val.w, h1, l1);
    reinterpret_cast<uint32_t*>(hi)[idx * 2 + 0] = h0;
    reinterpret_cast<uint32_t*>(hi)[idx * 2 + 1] = h1;
    reinterpret_cast<uint32_t*>(lo)[idx * 2 + 0] = l0;
    reinterpret_cast<uint32_t*>(lo)[idx * 2 + 1] = l1;
}

// ALL four W[K,N] -> Wt_hi/lo[N][K] transposes in ONE launch (3072 blocks).
// [0,1024): Wq, [1024,1536): Wk, [1536,2048): Wv, [2048,3072): Wo.
__global__ void __launch_bounds__(256) transpose_all_kernel(
    const float* __restrict__ Wq, __nv_bfloat16* __restrict__ Wqh, __nv_bfloat16* __restrict__ Wql,
    const float* __restrict__ Wk, __nv_bfloat16* __restrict__ Wkh, __nv_bfloat16* __restrict__ Wkl,
    const float* __restrict__ Wv, __nv_bfloat16* __restrict__ Wvh, __nv_bfloat16* __restrict__ Wvl,
    const float* __restrict__ Wo, __nv_bfloat16* __restrict__ Woh, __nv_bfloat16* __restrict__ Wol)
{
    __shared__ float t[32][33];
    const int N = DMODEL;
    int g = blockIdx.x;
    const float* W; __nv_bfloat16 *Th, *Tl; int K;
    if (g < 1024)      { W = Wq; Th = Wqh; Tl = Wql; K = DMODEL; }
    else if (g < 1536) { W = Wk; Th = Wkh; Tl = Wkl; K = IMGM; g -= 1024; }
    else if (g < 2048) { W = Wv; Th = Wvh; Tl = Wvl; K = IMGM; g -= 1536; }
    else               { W = Wo; Th = Woh; Tl = Wol; K = DMODEL; g -= 2048; }
    const int nx = N / 32;
    const int n0 = (g % nx) * 32, k0 = (g / nx) * 32;
    const int tx = threadIdx.x & 31, ty = threadIdx.x >> 5;  // 32 x 8
    #pragma unroll
    for (int i = ty; i < 32; i += 8)
        t[i][tx] = W[(size_t)(k0 + i) * N + n0 + tx];
    __syncthreads();
    #pragma unroll
    for (int i = ty; i < 32; i += 8) {
        float x = t[tx][i];
        __nv_bfloat16 h = __float2bfloat16_rn(x);
        float hf = __bfloat162float(h);
        Th[(size_t)(n0 + i) * K + k0 + tx] = h;
        Tl[(size_t)(n0 + i) * K + k0 + tx] = __float2bfloat16_rn(x - hf);
    }
}

// ---------------------------------------------------------------------------
// Flash attention on mma.sync (bf16 hi/lo, 3-term), KV tile = 128 (NT=8):
// half the softmax/barrier overhead per element vs KV=64.
// CTA: 128 queries x one (b,h). 8 warps, each owns 16 q rows.
// ---------------------------------------------------------------------------
#define AT_PAD     72
#define AT_Q_B     (128 * AT_PAD * 2)   // 18432
#define AT_KV_T    (128 * AT_PAD * 2)   // 18432 per tile (128 rows)
#define AT_STAGE   (4 * AT_KV_T)        // 73728 (Kh,Kl,Vh,Vl)
#define AT_SMEM    (2 * AT_Q_B + 2 * AT_STAGE)  // 184320

__device__ __forceinline__ void at_load_kv(
    uint32_t stage, const __nv_bfloat16* __restrict__ Kh,
    const __nv_bfloat16* __restrict__ Kl, const __nv_bfloat16* __restrict__ Vh,
    const __nv_bfloat16* __restrict__ Vl,
    int b, int colbase, int kv0, int tid)
{
    const __nv_bfloat16* srcs[4] = {Kh, Kl, Vh, Vl};
    #pragma unroll
    for (int i = 0; i < 16; i++) {
        int cid  = i * 256 + tid;       // 0..4095
        int tile = cid >> 10;           // 0..3
        int c    = cid & 1023;
        int row  = c >> 3;              // 0..127
        int ch   = c & 7;               // 16B chunk
        uint32_t dst = stage + tile * AT_KV_T + (uint32_t)(row * AT_PAD + ch * 8) * 2;
        const __nv_bfloat16* src = srcs[tile]
            + ((size_t)b * LKV_ + kv0 + row) * DMODEL + colbase + ch * 8;
        CP_ASYNC16(dst, src);
    }
}

__global__ void __launch_bounds__(256) attn_mma_kernel(
    const __nv_bfloat16* __restrict__ Qh_g, const __nv_bfloat16* __restrict__ Ql_g,
    const __nv_bfloat16* __restrict__ Kh_g, const __nv_bfloat16* __restrict__ Kl_g,
    const __nv_bfloat16* __restrict__ Vh_g, const __nv_bfloat16* __restrict__ Vl_g,
    __nv_bfloat16* __restrict__ Oh_g, __nv_bfloat16* __restrict__ Ol_g)
{
    extern __shared__ char smem[];
    const uint32_t sb  = smem_u32(smem);
    const uint32_t sQh = sb, sQl = sb + AT_Q_B;
    const uint32_t sKV = sb + 2 * AT_Q_B;

    const int qt = blockIdx.x, h = blockIdx.y, b = blockIdx.z;
    const int tid = threadIdx.x, lane = tid & 31, warp = tid >> 5;
    const int colbase = h * DK;
    const size_t qrow0 = (size_t)b * LQ_ + (size_t)qt * 128;

    // load Q hi/lo tiles (128 rows x 64 bf16)
    #pragma unroll
    for (int i = 0; i < 8; i++) {
        int cid = i * 256 + tid;
        int t   = cid >> 10;
        int c   = cid & 1023;
        int row = c >> 3;
        int ch  = c & 7;
        uint32_t dst = (t ? sQl : sQh) + (uint32_t)(row * AT_PAD + ch * 8) * 2;
        const __nv_bfloat16* src = (t ? Ql_g : Qh_g)
            + (qrow0 + row) * DMODEL + colbase + ch * 8;
        CP_ASYNC16(dst, src);
    }
    CP_COMMIT();

    at_load_kv(sKV, Kh_g, Kl_g, Vh_g, Vl_g, b, colbase, 0, tid);
    CP_COMMIT();

    const int a_r = lane & 15;
    const int a_c = (lane >> 4) * 8;
    const int b_r = lane & 7;
    const int b_c = ((lane >> 3) & 1) * 8;
    const int t_r = lane & 15;
    const float scale = 0.125f;

    float oacc[8][4];
    #pragma unroll
    for (int ng = 0; ng < 8; ng++)
        #pragma unroll
        for (int j = 0; j < 4; j++) oacc[ng][j] = 0.f;
    float m0 = -1e30f, m1 = -1e30f, l0 = 0.f, l1 = 0.f;

    const int NT = LKV_ / 128;           // 8 tiles
    for (int t = 0; t < NT; t++) {
        if (t + 1 < NT) {
            at_load_kv(sKV + ((t + 1) & 1) * AT_STAGE, Kh_g, Kl_g, Vh_g, Vl_g,
                       b, colbase, (t + 1) * 128, tid);
            CP_COMMIT();
            CP_WAIT(1);
        } else {
            CP_WAIT(0);
        }
        __syncthreads();

        const uint32_t st  = sKV + (t & 1) * AT_STAGE;
        const uint32_t tKh = st + 0 * AT_KV_T;
        const uint32_t tKl = st + 1 * AT_KV_T;
        const uint32_t tVh = st + 2 * AT_KV_T;
        const uint32_t tVl = st + 3 * AT_KV_T;

        // ---- S = Q K^T (3-term), 16 n-groups of 8 ----
        float sacc[16][4];
        #pragma unroll
        for (int ng = 0; ng < 16; ng++)
            #pragma unroll
            for (int j = 0; j < 4; j++) sacc[ng][j] = 0.f;

        #pragma unroll
        for (int kk = 0; kk < 4; kk++) {
            uint32_t qh4[4], ql4[4];
            uint32_t qoff = (uint32_t)((warp * 16 + a_r) * AT_PAD + kk * 16 + a_c) * 2;
            ldsm_x4(qh4, sQh + qoff);
            ldsm_x4(ql4, sQl + qoff);
            #pragma unroll
            for (int ng = 0; ng < 16; ng++) {
                uint32_t kh2[2], kl2[2];
                uint32_t koff = (uint32_t)((ng * 8 + b_r) * AT_PAD + kk * 16 + b_c) * 2;
                ldsm_x2(kh2, tKh + koff);
                ldsm_x2(kl2, tKl + koff);
                mma_bf16(sacc[ng], qh4, kh2);
                mma_bf16(sacc[ng], qh4, kl2);
                mma_bf16(sacc[ng], ql4, kh2);
            }
        }

        // ---- online softmax (warp-local) ----
        float mx0 = -1e30f, mx1 = -1e30f;
        #pragma unroll
        for (int ng = 0; ng < 16; ng++) {
            sacc[ng][0] *= scale; sacc[ng][1] *= scale;
            sacc[ng][2] *= scale; sacc[ng][3] *= scale;
            mx0 = fmaxf(mx0, fmaxf(sacc[ng][0], sacc[ng][1]));
            mx1 = fmaxf(mx1, fmaxf(sacc[ng][2], sacc[ng][3]));
        }
        mx0 = fmaxf(mx0, __shfl_xor_sync(0xFFFFFFFFu, mx0, 1));
        mx0 = fmaxf(mx0, __shfl_xor_sync(0xFFFFFFFFu, mx0, 2));
        mx1 = fmaxf(mx1, __shfl_xor_sync(0xFFFFFFFFu, mx1, 1));
        mx1 = fmaxf(mx1, __shfl_xor_sync(0xFFFFFFFFu, mx1, 2));

        float mn0 = fmaxf(m0, mx0), mn1 = fmaxf(m1, mx1);
        float corr0 = __expf(m0 - mn0), corr1 = __expf(m1 - mn1);
        float sum0 = 0.f, sum1 = 0.f;
        #pragma unroll
        for (int ng = 0; ng < 16; ng++) {
            float p0 = __expf(sacc[ng][0] - mn0);
            float p1 = __expf(sacc[ng][1] - mn0);
            float p2 = __expf(sacc[ng][2] - mn1);
            float p3 = __expf(sacc[ng][3] - mn1);
            sacc[ng][0] = p0; sacc[ng][1] = p1;
            sacc[ng][2] = p2; sacc[ng][3] = p3;
            sum0 += p0 + p1; sum1 += p2 + p3;
        }
        sum0 += __shfl_xor_sync(0xFFFFFFFFu, sum0, 1);
        sum0 += __shfl_xor_sync(0xFFFFFFFFu, sum0, 2);
        sum1 += __shfl_xor_sync(0xFFFFFFFFu, sum1, 1);
        sum1 += __shfl_xor_sync(0xFFFFFFFFu, sum1, 2);
        l0 = l0 * corr0 + sum0; m0 = mn0;
        l1 = l1 * corr1 + sum1; m1 = mn1;
        #pragma unroll
        for (int ng = 0; ng < 8; ng++) {
            oacc[ng][0] *= corr0; oacc[ng][1] *= corr0;
            oacc[ng][2] *= corr1; oacc[ng][3] *= corr1;
        }

        // ---- P repack: C frags -> A frags (hi/lo), 8 k-chunks ----
        uint32_t ph[8][4], pl[8][4];
        #pragma unroll
        for (int j = 0; j < 8; j++) {
            bf16_split_pack(sacc[2*j  ][0], sacc[2*j  ][1], ph[j][0], pl[j][0]);
            bf16_split_pack(sacc[2*j  ][2], sacc[2*j  ][3], ph[j][1], pl[j][1]);
            bf16_split_pack(sacc[2*j+1][0], sacc[2*j+1][1], ph[j][2], pl[j][2]);
            bf16_split_pack(sacc[2*j+1][2], sacc[2*j+1][3], ph[j][3], pl[j][3]);
        }

        // ---- O += P V (3-term); V via ldmatrix.trans ----
        #pragma unroll
        for (int j = 0; j < 8; j++) {
            #pragma unroll
            for (int ng = 0; ng < 8; ng++) {
                uint32_t vh2[2], vl2[2];
                uint32_t voff = (uint32_t)((j * 16 + t_r) * AT_PAD + ng * 8) * 2;
                ldsm_x2_trans(vh2, tVh + voff);
                ldsm_x2_trans(vl2, tVl + voff);
                mma_bf16(oacc[ng], ph[j], vh2);
                mma_bf16(oacc[ng], ph[j], vl2);
                mma_bf16(oacc[ng], pl[j], vh2);
            }
        }
        __syncthreads();
    }

    const float inv0 = 1.f / l0, inv1 = 1.f / l1;
    const int r0 = lane >> 2;
    const size_t row0 = (qrow0 + warp * 16 + r0) * DMODEL;
    const size_t row1 = row0 + 8 * DMODEL;
    #pragma unroll
    for (int ng = 0; ng < 8; ng++) {
        int col = colbase + ng * 8 + (lane & 3) * 2;
        uint32_t h0, lo0, h1, lo1;
        bf16_split_pack(oacc[ng][0] * inv0, oacc[ng][1] * inv0, h0, lo0);
        bf16_split_pack(oacc[ng][2] * inv1, oacc[ng][3] * inv1, h1, lo1);
        *reinterpret_cast<uint32_t*>(Oh_g + row0 + col) = h0;
        *reinterpret_cast<uint32_t*>(Ol_g + row0 + col) = lo0;
        *reinterpret_cast<uint32_t*>(Oh_g + row1 + col) = h1;
        *reinterpret_cast<uint32_t*>(Ol_g + row1 + col) = lo1;
    }
}

// ---------------------------------------------------------------------------
extern "C" void kernel_launch(void* const* d_in, const int* in_sizes, int n_in,
                              void* d_out, int out_size)
{
    const float* q  = (const float*)d_in[0];
    const float* k  = (const float*)d_in[1];
    const float* v  = (const float*)d_in[2];
    const float* Wq = (const float*)d_in[3];
    const float* bq = (const float*)d_in[4];
    const float* Wk = (const float*)d_in[5];
    const float* bk = (const float*)d_in[6];
    const float* Wv = (const float*)d_in[7];
    const float* bv = (const float*)d_in[8];
    const float* Wo = (const float*)d_in[9];
    const float* bo = (const float*)d_in[10];
    float* out = (float*)d_out;

    __nv_bfloat16 *qh, *ql, *kh, *kl, *vh, *vl, *ch, *cl;
    __nv_bfloat16 *Qph, *Qpl, *Kph, *Kpl, *Vph, *Vpl;
    __nv_bfloat16 *Wqh, *Wql, *Wkh, *Wkl, *Wvh, *Wvl, *Woh, *Wol;
    cudaGetSymbolAddress((void**)&qh, g_q_hi);  cudaGetSymbolAddress((void**)&ql, g_q_lo);
    cudaGetSymbolAddress((void**)&kh, g_k_hi);  cudaGetSymbolAddress((void**)&kl, g_k_lo);
    cudaGetSymbolAddress((void**)&vh, g_v_hi);  cudaGetSymbolAddress((void**)&vl, g_v_lo);
    cudaGetSymbolAddress((void**)&ch, g_c_hi);  cudaGetSymbolAddress((void**)&cl, g_c_lo);
    cudaGetSymbolAddress((void**)&Qph, g_Qph);  cudaGetSymbolAddress((void**)&Qpl, g_Qpl);
    cudaGetSymbolAddress((void**)&Kph, g_Kph);  cudaGetSymbolAddress((void**)&Kpl, g_Kpl);
    cudaGetSymbolAddress((void**)&Vph, g_Vph);  cudaGetSymbolAddress((void**)&Vpl, g_Vpl);
    cudaGetSymbolAddress((void**)&Wqh, g_Wqt_hi); cudaGetSymbolAddress((void**)&Wql, g_Wqt_lo);
    cudaGetSymbolAddress((void**)&Wkh, g_Wkt_hi); cudaGetSymbolAddress((void**)&Wkl, g_Wkt_lo);
    cudaGetSymbolAddress((void**)&Wvh, g_Wvt_hi); cudaGetSymbolAddress((void**)&Wvl, g_Wvt_lo);
    cudaGetSymbolAddress((void**)&Woh, g_Wot_hi); cudaGetSymbolAddress((void**)&Wol, g_Wot_lo);

    cudaFuncSetAttribute(proj_qkv_kernel,
                         cudaFuncAttributeMaxDynamicSharedMemorySize, GT_SMEM_TOTAL);
    cudaFuncSetAttribute(gemm_tc_kernel,
                         cudaFuncAttributeMaxDynamicSharedMemorySize, GT_SMEM_TOTAL);
    cudaFuncSetAttribute(attn_mma_kernel,
                         cudaFuncAttributeMaxDynamicSharedMemorySize, AT_SMEM);

    // launch 0: merged input splits (q, k, v)
    {
        int nblk = (Q4 + 2 * KV4 + 255) / 256;
        split_all_kernel<<<nblk, 256>>>(q, qh, ql, k, kh, kl, v, vh, vl);
    }
    // launch 1: ALL weight transposes (Wq, Wk, Wv, Wo) in one launch
    transpose_all_kernel<<<3072, 256>>>(Wq, Wqh, Wql, Wk, Wkh, Wkl,
                                        Wv, Wvh, Wvl, Wo, Woh, Wol);
    // launch 2: merged Q/K/V projection (1024 CTAs)
    proj_qkv_kernel<<<1024, 256, GT_SMEM_TOTAL>>>(
        qh, ql, Wqh, Wql, bq, Qph, Qpl,
        kh, kl, Wkh, Wkl, bk, Kph, Kpl,
        vh, vl, Wvh, Wvl, bv, Vph, Vpl);
    // launch 3: fused flash attention (KV tile 128)  <-- ncu capture slot
    attn_mma_kernel<<<dim3(LQ_ / 128, NHEADS, BATCH), 256, AT_SMEM>>>(
        Qph, Qpl, Kph, Kpl, Vph, Vpl, ch, cl);
    // launch 4: output projection (fp32 out)
    gemm_tc_kernel<<<dim3(DMODEL / 256, MQ / 128), 256, GT_SMEM_TOTAL>>>(
        ch, cl, Woh, Wol, bo, out, MQ, DMODEL, DMODEL);
}

// round 16
// speedup vs baseline: 1.0612x; 1.0612x over previous
#include <cuda_runtime.h>
#include <cuda_bf16.h>
#include <cstdint>
#include <math.h>

#define DMODEL 1024
#define IMGM   512
#define NHEADS 16
#define DK     64
#define BATCH  8
#define LQ_    2048
#define LKV_   1024
#define MQ   (BATCH * LQ_)    // 16384
#define MKV  (BATCH * LKV_)   // 8192

// ---------------- scratch (static device globals; no allocs allowed) -------
__device__ __nv_bfloat16 g_q_hi[(size_t)MQ  * DMODEL], g_q_lo[(size_t)MQ  * DMODEL];
__device__ __nv_bfloat16 g_k_hi[(size_t)MKV * IMGM ], g_k_lo[(size_t)MKV * IMGM ];
__device__ __nv_bfloat16 g_v_hi[(size_t)MKV * IMGM ], g_v_lo[(size_t)MKV * IMGM ];
__device__ __nv_bfloat16 g_Qph[(size_t)MQ  * DMODEL], g_Qpl[(size_t)MQ  * DMODEL];
__device__ __nv_bfloat16 g_Kph[(size_t)MKV * DMODEL], g_Kpl[(size_t)MKV * DMODEL];
__device__ __nv_bfloat16 g_Vph[(size_t)MKV * DMODEL], g_Vpl[(size_t)MKV * DMODEL];
__device__ __nv_bfloat16 g_c_hi[(size_t)MQ  * DMODEL], g_c_lo[(size_t)MQ  * DMODEL];
__device__ __nv_bfloat16 g_Wqt_hi[DMODEL * DMODEL], g_Wqt_lo[DMODEL * DMODEL];
__device__ __nv_bfloat16 g_Wkt_hi[DMODEL * IMGM ], g_Wkt_lo[DMODEL * IMGM ];
__device__ __nv_bfloat16 g_Wvt_hi[DMODEL * IMGM ], g_Wvt_lo[DMODEL * IMGM ];
__device__ __nv_bfloat16 g_Wot_hi[DMODEL * DMODEL], g_Wot_lo[DMODEL * DMODEL];

// ---------------- PTX helpers ----------------------------------------------
__device__ __forceinline__ uint32_t smem_u32(const void* p) {
    uint32_t a;
    asm("{ .reg .u64 t; cvta.to.shared.u64 t, %1; cvt.u32.u64 %0, t; }"
        : "=r"(a) : "l"(p));
    return a;
}
__device__ __forceinline__ void ldsm_x4(uint32_t* r, uint32_t addr) {
    asm volatile("ldmatrix.sync.aligned.m8n8.x4.shared.b16 {%0,%1,%2,%3}, [%4];"
                 : "=r"(r[0]), "=r"(r[1]), "=r"(r[2]), "=r"(r[3]) : "r"(addr));
}
__device__ __forceinline__ void ldsm_x2(uint32_t* r, uint32_t addr) {
    asm volatile("ldmatrix.sync.aligned.m8n8.x2.shared.b16 {%0,%1}, [%2];"
                 : "=r"(r[0]), "=r"(r[1]) : "r"(addr));
}
__device__ __forceinline__ void ldsm_x2_trans(uint32_t* r, uint32_t addr) {
    asm volatile("ldmatrix.sync.aligned.m8n8.x2.trans.shared.b16 {%0,%1}, [%2];"
                 : "=r"(r[0]), "=r"(r[1]) : "r"(addr));
}
__device__ __forceinline__ void mma_bf16(float* c, const uint32_t* a, const uint32_t* b) {
    asm volatile(
        "mma.sync.aligned.m16n8k16.row.col.f32.bf16.bf16.f32 "
        "{%0,%1,%2,%3}, {%4,%5,%6,%7}, {%8,%9}, {%0,%1,%2,%3};"
        : "+f"(c[0]), "+f"(c[1]), "+f"(c[2]), "+f"(c[3])
        : "r"(a[0]), "r"(a[1]), "r"(a[2]), "r"(a[3]), "r"(b[0]), "r"(b[1]));
}
#define CP_ASYNC16(dst, src) \
    asm volatile("cp.async.cg.shared.global [%0], [%1], 16;" :: "r"(dst), "l"(src) : "memory")
#define CP_COMMIT()  asm volatile("cp.async.commit_group;" ::: "memory")
#define CP_WAIT(n)   asm volatile("cp.async.wait_group %0;" :: "n"(n) : "memory")

__device__ __forceinline__ void bf16_split_pack(float a, float b,
                                                uint32_t& hi, uint32_t& lo) {
    __nv_bfloat16 ha = __float2bfloat16_rn(a), hb = __float2bfloat16_rn(b);
    float ra = a - __bfloat162float(ha);
    float rb = b - __bfloat162float(hb);
    __nv_bfloat162 hp, lp;
    hp.x = ha; hp.y = hb;
    lp.x = __float2bfloat16_rn(ra); lp.y = __float2bfloat16_rn(rb);
    hi = *reinterpret_cast<uint32_t*>(&hp);
    lo = *reinterpret_cast<uint32_t*>(&lp);
}

// ---------------------------------------------------------------------------
// HMMA bf16 GEMM core (round-7/14 best): CTA 128(M) x 256(N), BK=64,
// 256 threads, 8 warps 2(M) x 4(N), warp tile 64x64. Double-buffered cp.async.
// ---------------------------------------------------------------------------
#define GT_PAD      72
#define GT_ATILE_B  (128 * GT_PAD * 2)   // 18432
#define GT_BTILE_B  (256 * GT_PAD * 2)   // 36864
#define GT_STAGE_B  (2 * GT_ATILE_B + 2 * GT_BTILE_B)   // 110592
#define GT_SMEM_TOTAL (2 * GT_STAGE_B)                  // 221184

__device__ __forceinline__ void gt_load_stage(
    uint32_t stage, const __nv_bfloat16* __restrict__ Ah,
    const __nv_bfloat16* __restrict__ Al, const __nv_bfloat16* __restrict__ Bh,
    const __nv_bfloat16* __restrict__ Bl,
    int bm, int bn, int K, int k0, int tid)
{
    #pragma unroll
    for (int i = 0; i < 24; i++) {
        int cid = i * 256 + tid;        // 0..6143
        int ch  = cid & 7;              // 16B chunk within 64-col row
        uint32_t dst;
        const __nv_bfloat16* src;
        if (cid < 2048) {               // A region: hi 0-1023, lo 1024-2047
            int row = (cid >> 3) & 127;
            bool hi = cid < 1024;
            src = (hi ? Ah : Al) + (size_t)(bm + row) * K + k0 + ch * 8;
            dst = stage + (hi ? 0u : (uint32_t)GT_ATILE_B)
                + (uint32_t)(row * GT_PAD + ch * 8) * 2;
        } else {                        // B region: hi 0-2047, lo 2048-4095
            int c2  = cid - 2048;
            int row = (c2 >> 3) & 255;
            bool hi = c2 < 2048;
            src = (hi ? Bh : Bl) + (size_t)(bn + row) * K + k0 + ch * 8;
            dst = stage + 2u * GT_ATILE_B + (hi ? 0u : (uint32_t)GT_BTILE_B)
                + (uint32_t)(row * GT_PAD + ch * 8) * 2;
        }
        CP_ASYNC16(dst, src);
    }
}

__device__ __forceinline__ void gemm_core(
    const __nv_bfloat16* __restrict__ Ah, const __nv_bfloat16* __restrict__ Al,
    const __nv_bfloat16* __restrict__ Bh, const __nv_bfloat16* __restrict__ Bl,
    const float* __restrict__ bias, float* __restrict__ C,
    __nv_bfloat16* __restrict__ Chi, __nv_bfloat16* __restrict__ Clo,
    int N, int K, int bm, int bn, uint32_t sb, int tid)
{
    const int lane = tid & 31;
    const int wid  = tid >> 5;
    const int wm   = wid & 1;
    const int wn   = wid >> 1;

    float acc[4][8][4];
    #pragma unroll
    for (int mt = 0; mt < 4; mt++)
        #pragma unroll
        for (int nt = 0; nt < 8; nt++)
            #pragma unroll
            for (int j = 0; j < 4; j++) acc[mt][nt][j] = 0.f;

    const int KT = K >> 6;

    gt_load_stage(sb, Ah, Al, Bh, Bl, bm, bn, K, 0, tid);
    CP_COMMIT();

    const int a_r = lane & 15;
    const int a_c = (lane >> 4) * 8;
    const int b_row_l = ((lane >> 4) & 1) * 8 + (lane & 7);
    const int b_col_l = ((lane >> 3) & 1) * 8;

    for (int s = 0; s < KT; s++) {
        if (s + 1 < KT) {
            gt_load_stage(sb + ((s + 1) & 1) * GT_STAGE_B, Ah, Al, Bh, Bl,
                          bm, bn, K, (s + 1) * 64, tid);
            CP_COMMIT();
            CP_WAIT(1);
        } else {
            CP_WAIT(0);
        }
        __syncthreads();

        const uint32_t st  = sb + (s & 1) * GT_STAGE_B;
        const uint32_t sAh = st;
        const uint32_t sAl = st + GT_ATILE_B;
        const uint32_t sBh = st + 2 * GT_ATILE_B;
        const uint32_t sBl = st + 2 * GT_ATILE_B + GT_BTILE_B;

        #pragma unroll
        for (int kk = 0; kk < 4; kk++) {
            uint32_t ah[4][4], al[4][4];
            #pragma unroll
            for (int mt = 0; mt < 4; mt++) {
                uint32_t off = (uint32_t)((wm * 64 + mt * 16 + a_r) * GT_PAD
                                          + kk * 16 + a_c) * 2;
                ldsm_x4(ah[mt], sAh + off);
                ldsm_x4(al[mt], sAl + off);
            }
            #pragma unroll
            for (int p = 0; p < 4; p++) {
                uint32_t bh4[4], bl4[4];
                uint32_t off = (uint32_t)((wn * 64 + p * 16 + b_row_l) * GT_PAD
                                          + kk * 16 + b_col_l) * 2;
                ldsm_x4(bh4, sBh + off);
                ldsm_x4(bl4, sBl + off);
                #pragma unroll
                for (int mt = 0; mt < 4; mt++) {
                    mma_bf16(acc[mt][2*p  ], ah[mt], &bh4[0]);
                    mma_bf16(acc[mt][2*p  ], ah[mt], &bl4[0]);
                    mma_bf16(acc[mt][2*p  ], al[mt], &bh4[0]);
                    mma_bf16(acc[mt][2*p+1], ah[mt], &bh4[2]);
                    mma_bf16(acc[mt][2*p+1], ah[mt], &bl4[2]);
                    mma_bf16(acc[mt][2*p+1], al[mt], &bh4[2]);
                }
            }
        }
        __syncthreads();
    }

    const int er = lane >> 2;
    const int ec = (lane & 3) * 2;
    #pragma unroll
    for (int mt = 0; mt < 4; mt++) {
        #pragma unroll
        for (int nt = 0; nt < 8; nt++) {
            int row0 = bm + wm * 64 + mt * 16 + er;
            int col  = bn + wn * 64 + nt * 8 + ec;
            float b0 = bias[col], b1 = bias[col + 1];
            float v00 = acc[mt][nt][0] + b0, v01 = acc[mt][nt][1] + b1;
            float v10 = acc[mt][nt][2] + b0, v11 = acc[mt][nt][3] + b1;
            if (Chi) {
                uint32_t h0, l0, h1, l1;
                bf16_split_pack(v00, v01, h0, l0);
                bf16_split_pack(v10, v11, h1, l1);
                *reinterpret_cast<uint32_t*>(Chi + (size_t)row0 * N + col)       = h0;
                *reinterpret_cast<uint32_t*>(Clo + (size_t)row0 * N + col)       = l0;
                *reinterpret_cast<uint32_t*>(Chi + (size_t)(row0 + 8) * N + col) = h1;
                *reinterpret_cast<uint32_t*>(Clo + (size_t)(row0 + 8) * N + col) = l1;
            } else {
                float2 w0, w1;
                w0.x = v00; w0.y = v01; w1.x = v10; w1.y = v11;
                *reinterpret_cast<float2*>(C + (size_t)row0 * N + col)       = w0;
                *reinterpret_cast<float2*>(C + (size_t)(row0 + 8) * N + col) = w1;
            }
        }
    }
}

// Merged Q/K/V projection: one launch, 1024 CTAs.
__global__ void __launch_bounds__(256, 1) proj_qkv_kernel(
    const __nv_bfloat16* __restrict__ qh, const __nv_bfloat16* __restrict__ ql,
    const __nv_bfloat16* __restrict__ Wqh, const __nv_bfloat16* __restrict__ Wql,
    const float* __restrict__ bq,
    __nv_bfloat16* __restrict__ Qph, __nv_bfloat16* __restrict__ Qpl,
    const __nv_bfloat16* __restrict__ kh, const __nv_bfloat16* __restrict__ kl,
    const __nv_bfloat16* __restrict__ Wkh, const __nv_bfloat16* __restrict__ Wkl,
    const float* __restrict__ bk,
    __nv_bfloat16* __restrict__ Kph, __nv_bfloat16* __restrict__ Kpl,
    const __nv_bfloat16* __restrict__ vh, const __nv_bfloat16* __restrict__ vl,
    const __nv_bfloat16* __restrict__ Wvh, const __nv_bfloat16* __restrict__ Wvl,
    const float* __restrict__ bv,
    __nv_bfloat16* __restrict__ Vph, __nv_bfloat16* __restrict__ Vpl)
{
    extern __shared__ char smem[];
    const uint32_t sb = smem_u32(smem);
    const int tid = threadIdx.x;
    const int gid = blockIdx.x;

    int op, t;
    if (gid < 512)      { op = 0; t = gid; }
    else if (gid < 768) { op = 1; t = gid - 512; }
    else                { op = 2; t = gid - 768; }

    const __nv_bfloat16* Ah = (op == 0) ? qh  : (op == 1) ? kh  : vh;
    const __nv_bfloat16* Al = (op == 0) ? ql  : (op == 1) ? kl  : vl;
    const __nv_bfloat16* Bh = (op == 0) ? Wqh : (op == 1) ? Wkh : Wvh;
    const __nv_bfloat16* Bl = (op == 0) ? Wql : (op == 1) ? Wkl : Wvl;
    const float*        bias = (op == 0) ? bq  : (op == 1) ? bk  : bv;
    __nv_bfloat16*      Chi = (op == 0) ? Qph : (op == 1) ? Kph : Vph;
    __nv_bfloat16*      Clo = (op == 0) ? Qpl : (op == 1) ? Kpl : Vpl;
    const int K = (op == 0) ? DMODEL : IMGM;

    const int bn = (t & 3) * 256;
    const int bm = (t >> 2) * 128;

    gemm_core(Ah, Al, Bh, Bl, bias, nullptr, Chi, Clo, DMODEL, K, bm, bn, sb, tid);
}

// Single GEMM launch (O-projection, fp32 output)
__global__ void __launch_bounds__(256, 1) gemm_tc_kernel(
    const __nv_bfloat16* __restrict__ Ah, const __nv_bfloat16* __restrict__ Al,
    const __nv_bfloat16* __restrict__ Bh, const __nv_bfloat16* __restrict__ Bl,
    const float* __restrict__ bias, float* __restrict__ C,
    int M, int N, int K)
{
    extern __shared__ char smem[];
    const uint32_t sb = smem_u32(smem);
    const int bn = blockIdx.x * 256;
    const int bm = blockIdx.y * 128;
    gemm_core(Ah, Al, Bh, Bl, bias, C, nullptr, nullptr, N, K, bm, bn, sb, threadIdx.x);
}

// ---------------------------------------------------------------------------
// Merged fp32 -> bf16 hi/lo split for q, k, v (one launch)
// ---------------------------------------------------------------------------
#define Q4  (MQ  * DMODEL / 4)
#define KV4 (MKV * IMGM  / 4)

__global__ void __launch_bounds__(256) split_all_kernel(
    const float* __restrict__ q, __nv_bfloat16* __restrict__ qh, __nv_bfloat16* __restrict__ ql,
    const float* __restrict__ k, __nv_bfloat16* __restrict__ kh, __nv_bfloat16* __restrict__ kl,
    const float* __restrict__ v, __nv_bfloat16* __restrict__ vh, __nv_bfloat16* __restrict__ vl)
{
    int i = blockIdx.x * 256 + threadIdx.x;
    const float* x; __nv_bfloat16 *hi, *lo; int idx;
    if (i < Q4)                { x = q; hi = qh; lo = ql; idx = i; }
    else if (i < Q4 + KV4)     { x = k; hi = kh; lo = kl; idx = i - Q4; }
    else if (i < Q4 + 2 * KV4) { x = v; hi = vh; lo = vl; idx = i - Q4 - KV4; }
    else return;
    float4 val = reinterpret_cast<const float4*>(x)[idx];
    uint32_t h0, l0, h1, l1;
    bf16_split_pack(val.x, val.y, h0, l0);
    bf16_split_pack(val.z, val.w, h1, l1);
    reinterpret_cast<uint32_t*>(hi)[idx * 2 + 0] = h0;
    reinterpret_cast<uint32_t*>(hi)[idx * 2 + 1] = h1;
    reinterpret_cast<uint32_t*>(lo)[idx * 2 + 0] = l0;
    reinterpret_cast<uint32_t*>(lo)[idx * 2 + 1] = l1;
}

// ALL four W[K,N] -> Wt_hi/lo[N][K] transposes in ONE launch (3072 blocks).
__global__ void __launch_bounds__(256) transpose_all_kernel(
    const float* __restrict__ Wq, __nv_bfloat16* __restrict__ Wqh, __nv_bfloat16* __restrict__ Wql,
    const float* __restrict__ Wk, __nv_bfloat16* __restrict__ Wkh, __nv_bfloat16* __restrict__ Wkl,
    const float* __restrict__ Wv, __nv_bfloat16* __restrict__ Wvh, __nv_bfloat16* __restrict__ Wvl,
    const float* __restrict__ Wo, __nv_bfloat16* __restrict__ Woh, __nv_bfloat16* __restrict__ Wol)
{
    __shared__ float t[32][33];
    const int N = DMODEL;
    int g = blockIdx.x;
    const float* W; __nv_bfloat16 *Th, *Tl; int K;
    if (g < 1024)      { W = Wq; Th = Wqh; Tl = Wql; K = DMODEL; }
    else if (g < 1536) { W = Wk; Th = Wkh; Tl = Wkl; K = IMGM; g -= 1024; }
    else if (g < 2048) { W = Wv; Th = Wvh; Tl = Wvl; K = IMGM; g -= 1536; }
    else               { W = Wo; Th = Woh; Tl = Wol; K = DMODEL; g -= 2048; }
    const int nx = N / 32;
    const int n0 = (g % nx) * 32, k0 = (g / nx) * 32;
    const int tx = threadIdx.x & 31, ty = threadIdx.x >> 5;  // 32 x 8
    #pragma unroll
    for (int i = ty; i < 32; i += 8)
        t[i][tx] = W[(size_t)(k0 + i) * N + n0 + tx];
    __syncthreads();
    #pragma unroll
    for (int i = ty; i < 32; i += 8) {
        float x = t[tx][i];
        __nv_bfloat16 h = __float2bfloat16_rn(x);
        float hf = __bfloat162float(h);
        Th[(size_t)(n0 + i) * K + k0 + tx] = h;
        Tl[(size_t)(n0 + i) * K + k0 + tx] = __float2bfloat16_rn(x - hf);
    }
}

// ---------------------------------------------------------------------------
// Flash attention on mma.sync (bf16 hi/lo, 3-term), KV tile = 64 (NT=16):
// the round-14 best-measured configuration, restored verbatim.
// ---------------------------------------------------------------------------
#define AT_PAD     72
#define AT_Q_B     (128 * AT_PAD * 2)
#define AT_KV_T    (64 * AT_PAD * 2)
#define AT_STAGE   (4 * AT_KV_T)
#define AT_SMEM    (2 * AT_Q_B + 2 * AT_STAGE)  // 110592

__device__ __forceinline__ void at_load_kv(
    uint32_t stage, const __nv_bfloat16* __restrict__ Kh,
    const __nv_bfloat16* __restrict__ Kl, const __nv_bfloat16* __restrict__ Vh,
    const __nv_bfloat16* __restrict__ Vl,
    int b, int colbase, int kv0, int tid)
{
    const __nv_bfloat16* srcs[4] = {Kh, Kl, Vh, Vl};
    #pragma unroll
    for (int i = 0; i < 8; i++) {
        int cid  = i * 256 + tid;
        int tile = cid >> 9;
        int c    = cid & 511;
        int row  = c >> 3;
        int ch   = c & 7;
        uint32_t dst = stage + tile * AT_KV_T + (uint32_t)(row * AT_PAD + ch * 8) * 2;
        const __nv_bfloat16* src = srcs[tile]
            + ((size_t)b * LKV_ + kv0 + row) * DMODEL + colbase + ch * 8;
        CP_ASYNC16(dst, src);
    }
}

__global__ void __launch_bounds__(256) attn_mma_kernel(
    const __nv_bfloat16* __restrict__ Qh_g, const __nv_bfloat16* __restrict__ Ql_g,
    const __nv_bfloat16* __restrict__ Kh_g, const __nv_bfloat16* __restrict__ Kl_g,
    const __nv_bfloat16* __restrict__ Vh_g, const __nv_bfloat16* __restrict__ Vl_g,
    __nv_bfloat16* __restrict__ Oh_g, __nv_bfloat16* __restrict__ Ol_g)
{
    extern __shared__ char smem[];
    const uint32_t sb  = smem_u32(smem);
    const uint32_t sQh = sb, sQl = sb + AT_Q_B;
    const uint32_t sKV = sb + 2 * AT_Q_B;

    const int qt = blockIdx.x, h = blockIdx.y, b = blockIdx.z;
    const int tid = threadIdx.x, lane = tid & 31, warp = tid >> 5;
    const int colbase = h * DK;
    const size_t qrow0 = (size_t)b * LQ_ + (size_t)qt * 128;

    #pragma unroll
    for (int i = 0; i < 8; i++) {
        int cid = i * 256 + tid;
        int t   = cid >> 10;
        int c   = cid & 1023;
        int row = c >> 3;
        int ch  = c & 7;
        uint32_t dst = (t ? sQl : sQh) + (uint32_t)(row * AT_PAD + ch * 8) * 2;
        const __nv_bfloat16* src = (t ? Ql_g : Qh_g)
            + (qrow0 + row) * DMODEL + colbase + ch * 8;
        CP_ASYNC16(dst, src);
    }
    CP_COMMIT();

    at_load_kv(sKV, Kh_g, Kl_g, Vh_g, Vl_g, b, colbase, 0, tid);
    CP_COMMIT();

    const int a_r = lane & 15;
    const int a_c = (lane >> 4) * 8;
    const int b_r = lane & 7;
    const int b_c = ((lane >> 3) & 1) * 8;
    const int t_r = lane & 15;
    const float scale = 0.125f;

    float oacc[8][4];
    #pragma unroll
    for (int ng = 0; ng < 8; ng++)
        #pragma unroll
        for (int j = 0; j < 4; j++) oacc[ng][j] = 0.f;
    float m0 = -1e30f, m1 = -1e30f, l0 = 0.f, l1 = 0.f;

    const int NT = LKV_ / 64;
    for (int t = 0; t < NT; t++) {
        if (t + 1 < NT) {
            at_load_kv(sKV + ((t + 1) & 1) * AT_STAGE, Kh_g, Kl_g, Vh_g, Vl_g,
                       b, colbase, (t + 1) * 64, tid);
            CP_COMMIT();
            CP_WAIT(1);
        } else {
            CP_WAIT(0);
        }
        __syncthreads();

        const uint32_t st  = sKV + (t & 1) * AT_STAGE;
        const uint32_t tKh = st + 0 * AT_KV_T;
        const uint32_t tKl = st + 1 * AT_KV_T;
        const uint32_t tVh = st + 2 * AT_KV_T;
        const uint32_t tVl = st + 3 * AT_KV_T;

        float sacc[8][4];
        #pragma unroll
        for (int ng = 0; ng < 8; ng++)
            #pragma unroll
            for (int j = 0; j < 4; j++) sacc[ng][j] = 0.f;

        #pragma unroll
        for (int kk = 0; kk < 4; kk++) {
            uint32_t qh4[4], ql4[4];
            uint32_t qoff = (uint32_t)((warp * 16 + a_r) * AT_PAD + kk * 16 + a_c) * 2;
            ldsm_x4(qh4, sQh + qoff);
            ldsm_x4(ql4, sQl + qoff);
            #pragma unroll
            for (int ng = 0; ng < 8; ng++) {
                uint32_t kh2[2], kl2[2];
                uint32_t koff = (uint32_t)((ng * 8 + b_r) * AT_PAD + kk * 16 + b_c) * 2;
                ldsm_x2(kh2, tKh + koff);
                ldsm_x2(kl2, tKl + koff);
                mma_bf16(sacc[ng], qh4, kh2);
                mma_bf16(sacc[ng], qh4, kl2);
                mma_bf16(sacc[ng], ql4, kh2);
            }
        }

        float mx0 = -1e30f, mx1 = -1e30f;
        #pragma unroll
        for (int ng = 0; ng < 8; ng++) {
            sacc[ng][0] *= scale; sacc[ng][1] *= scale;
            sacc[ng][2] *= scale; sacc[ng][3] *= scale;
            mx0 = fmaxf(mx0, fmaxf(sacc[ng][0], sacc[ng][1]));
            mx1 = fmaxf(mx1, fmaxf(sacc[ng][2], sacc[ng][3]));
        }
        mx0 = fmaxf(mx0, __shfl_xor_sync(0xFFFFFFFFu, mx0, 1));
        mx0 = fmaxf(mx0, __shfl_xor_sync(0xFFFFFFFFu, mx0, 2));
        mx1 = fmaxf(mx1, __shfl_xor_sync(0xFFFFFFFFu, mx1, 1));
        mx1 = fmaxf(mx1, __shfl_xor_sync(0xFFFFFFFFu, mx1, 2));

        float mn0 = fmaxf(m0, mx0), mn1 = fmaxf(m1, mx1);
        float corr0 = __expf(m0 - mn0), corr1 = __expf(m1 - mn1);
        float sum0 = 0.f, sum1 = 0.f;
        #pragma unroll
        for (int ng = 0; ng < 8; ng++) {
            float p0 = __expf(sacc[ng][0] - mn0);
            float p1 = __expf(sacc[ng][1] - mn0);
            float p2 = __expf(sacc[ng][2] - mn1);
            float p3 = __expf(sacc[ng][3] - mn1);
            sacc[ng][0] = p0; sacc[ng][1] = p1;
            sacc[ng][2] = p2; sacc[ng][3] = p3;
            sum0 += p0 + p1; sum1 += p2 + p3;
        }
        sum0 += __shfl_xor_sync(0xFFFFFFFFu, sum0, 1);
        sum0 += __shfl_xor_sync(0xFFFFFFFFu, sum0, 2);
        sum1 += __shfl_xor_sync(0xFFFFFFFFu, sum1, 1);
        sum1 += __shfl_xor_sync(0xFFFFFFFFu, sum1, 2);
        l0 = l0 * corr0 + sum0; m0 = mn0;
        l1 = l1 * corr1 + sum1; m1 = mn1;
        #pragma unroll
        for (int ng = 0; ng < 8; ng++) {
            oacc[ng][0] *= corr0; oacc[ng][1] *= corr0;
            oacc[ng][2] *= corr1; oacc[ng][3] *= corr1;
        }

        uint32_t ph[4][4], pl[4][4];
        #pragma unroll
        for (int j = 0; j < 4; j++) {
            bf16_split_pack(sacc[2*j  ][0], sacc[2*j  ][1], ph[j][0], pl[j][0]);
            bf16_split_pack(sacc[2*j  ][2], sacc[2*j  ][3], ph[j][1], pl[j][1]);
            bf16_split_pack(sacc[2*j+1][0], sacc[2*j+1][1], ph[j][2], pl[j][2]);
            bf16_split_pack(sacc[2*j+1][2], sacc[2*j+1][3], ph[j][3], pl[j][3]);
        }

        #pragma unroll
        for (int j = 0; j < 4; j++) {
            #pragma unroll
            for (int ng = 0; ng < 8; ng++) {
                uint32_t vh2[2], vl2[2];
                uint32_t voff = (uint32_t)((j * 16 + t_r) * AT_PAD + ng * 8) * 2;
                ldsm_x2_trans(vh2, tVh + voff);
                ldsm_x2_trans(vl2, tVl + voff);
                mma_bf16(oacc[ng], ph[j], vh2);
                mma_bf16(oacc[ng], ph[j], vl2);
                mma_bf16(oacc[ng], pl[j], vh2);
            }
        }
        __syncthreads();
    }

    const float inv0 = 1.f / l0, inv1 = 1.f / l1;
    const int r0 = lane >> 2;
    const size_t row0 = (qrow0 + warp * 16 + r0) * DMODEL;
    const size_t row1 = row0 + 8 * DMODEL;
    #pragma unroll
    for (int ng = 0; ng < 8; ng++) {
        int col = colbase + ng * 8 + (lane & 3) * 2;
        uint32_t h0, lo0, h1, lo1;
        bf16_split_pack(oacc[ng][0] * inv0, oacc[ng][1] * inv0, h0, lo0);
        bf16_split_pack(oacc[ng][2] * inv1, oacc[ng][3] * inv1, h1, lo1);
        *reinterpret_cast<uint32_t*>(Oh_g + row0 + col) = h0;
        *reinterpret_cast<uint32_t*>(Ol_g + row0 + col) = lo0;
        *reinterpret_cast<uint32_t*>(Oh_g + row1 + col) = h1;
        *reinterpret_cast<uint32_t*>(Ol_g + row1 + col) = lo1;
    }
}

// ---------------------------------------------------------------------------
extern "C" void kernel_launch(void* const* d_in, const int* in_sizes, int n_in,
                              void* d_out, int out_size)
{
    const float* q  = (const float*)d_in[0];
    const float* k  = (const float*)d_in[1];
    const float* v  = (const float*)d_in[2];
    const float* Wq = (const float*)d_in[3];
    const float* bq = (const float*)d_in[4];
    const float* Wk = (const float*)d_in[5];
    const float* bk = (const float*)d_in[6];
    const float* Wv = (const float*)d_in[7];
    const float* bv = (const float*)d_in[8];
    const float* Wo = (const float*)d_in[9];
    const float* bo = (const float*)d_in[10];
    float* out = (float*)d_out;

    __nv_bfloat16 *qh, *ql, *kh, *kl, *vh, *vl, *ch, *cl;
    __nv_bfloat16 *Qph, *Qpl, *Kph, *Kpl, *Vph, *Vpl;
    __nv_bfloat16 *Wqh, *Wql, *Wkh, *Wkl, *Wvh, *Wvl, *Woh, *Wol;
    cudaGetSymbolAddress((void**)&qh, g_q_hi);  cudaGetSymbolAddress((void**)&ql, g_q_lo);
    cudaGetSymbolAddress((void**)&kh, g_k_hi);  cudaGetSymbolAddress((void**)&kl, g_k_lo);
    cudaGetSymbolAddress((void**)&vh, g_v_hi);  cudaGetSymbolAddress((void**)&vl, g_v_lo);
    cudaGetSymbolAddress((void**)&ch, g_c_hi);  cudaGetSymbolAddress((void**)&cl, g_c_lo);
    cudaGetSymbolAddress((void**)&Qph, g_Qph);  cudaGetSymbolAddress((void**)&Qpl, g_Qpl);
    cudaGetSymbolAddress((void**)&Kph, g_Kph);  cudaGetSymbolAddress((void**)&Kpl, g_Kpl);
    cudaGetSymbolAddress((void**)&Vph, g_Vph);  cudaGetSymbolAddress((void**)&Vpl, g_Vpl);
    cudaGetSymbolAddress((void**)&Wqh, g_Wqt_hi); cudaGetSymbolAddress((void**)&Wql, g_Wqt_lo);
    cudaGetSymbolAddress((void**)&Wkh, g_Wkt_hi); cudaGetSymbolAddress((void**)&Wkl, g_Wkt_lo);
    cudaGetSymbolAddress((void**)&Wvh, g_Wvt_hi); cudaGetSymbolAddress((void**)&Wvl, g_Wvt_lo);
    cudaGetSymbolAddress((void**)&Woh, g_Wot_hi); cudaGetSymbolAddress((void**)&Wol, g_Wot_lo);

    cudaFuncSetAttribute(proj_qkv_kernel,
                         cudaFuncAttributeMaxDynamicSharedMemorySize, GT_SMEM_TOTAL);
    cudaFuncSetAttribute(gemm_tc_kernel,
                         cudaFuncAttributeMaxDynamicSharedMemorySize, GT_SMEM_TOTAL);
    cudaFuncSetAttribute(attn_mma_kernel,
                         cudaFuncAttributeMaxDynamicSharedMemorySize, AT_SMEM);

    // launch 0: merged input splits (q, k, v)
    {
        int nblk = (Q4 + 2 * KV4 + 255) / 256;
        split_all_kernel<<<nblk, 256>>>(q, qh, ql, k, kh, kl, v, vh, vl);
    }
    // launch 1: ALL weight transposes in one launch
    transpose_all_kernel<<<3072, 256>>>(Wq, Wqh, Wql, Wk, Wkh, Wkl,
                                        Wv, Wvh, Wvl, Wo, Woh, Wol);
    // launch 2: merged Q/K/V projection (1024 CTAs)
    proj_qkv_kernel<<<1024, 256, GT_SMEM_TOTAL>>>(
        qh, ql, Wqh, Wql, bq, Qph, Qpl,
        kh, kl, Wkh, Wkl, bk, Kph, Kpl,
        vh, vl, Wvh, Wvl, bv, Vph, Vpl);
    // launch 3: fused flash attention (KV tile 64)  <-- ncu capture slot
    attn_mma_kernel<<<dim3(LQ_ / 128, NHEADS, BATCH), 256, AT_SMEM>>>(
        Qph, Qpl, Kph, Kpl, Vph, Vpl, ch, cl);
    // launch 4: output projection (fp32 out)
    gemm_tc_kernel<<<dim3(DMODEL / 256, MQ / 128), 256, GT_SMEM_TOTAL>>>(
        ch, cl, Woh, Wol, bo, out, MQ, DMODEL, DMODEL);
}